// round 1
// baseline (speedup 1.0000x reference)
#include <cuda_runtime.h>
#include <cuda_bf16.h>
#include <cstdint>

// Problem constants
#define N_ROWS   131072
#define D_IN     512
#define D_H      1024
#define D_OUT    128
#define NUM_GROUPS 1024
#define LN_EPS   1e-5f

// ---------------------------------------------------------------------------
// Scratch: __device__ globals (no cudaMalloc allowed).
// h1, h2: [N_ROWS, D_H] fp32 activations. counts: per-group row counts.
// ---------------------------------------------------------------------------
__device__ float g_h1[(size_t)N_ROWS * D_H];
__device__ float g_h2[(size_t)N_ROWS * D_H];
__device__ float g_counts[NUM_GROUPS];

// ---------------------------------------------------------------------------
// SGEMM: C[M, Ncols] = A[M, K] @ B[K, Ncols], fused epilogues.
//   EPI == 0 : C = relu(A@B + bias), stored to C (ldc == ldb)
//   EPI == 1 : val = A@B + bias; atomicAdd into out[batch[row] * D_OUT + col]
// Tiling: BM=BN=128, BK=16, 256 threads, 8x8 micro-tile per thread with the
// split +-64 fragment layout (conflict-friendly vectorized smem reads).
// Assumes M % 128 == 0, Ncols % 128 == 0, K % 16 == 0 (true for all 3 GEMMs).
// ---------------------------------------------------------------------------
template <int EPI>
__global__ void __launch_bounds__(256, 2)
sgemm_fused(const float* __restrict__ A,
            const float* __restrict__ B,
            const float* __restrict__ bias,
            float* __restrict__ C,
            int K, int ldb,
            const int* __restrict__ batch,
            float* __restrict__ out)
{
    __shared__ float As[16][132];   // [k][m], padded to avoid store conflicts
    __shared__ float Bs[16][128];   // [k][n]

    const int tid = threadIdx.x;
    const int m0 = blockIdx.y * 128;
    const int n0 = blockIdx.x * 128;

    // A-tile loader mapping: each thread loads 2 rows x 4 contiguous k
    const int arow = tid >> 2;          // 0..63
    const int acol = (tid & 3) * 4;     // 0,4,8,12
    // B-tile loader mapping: each thread loads 2 rows x 4 contiguous n
    const int brow = tid >> 5;          // 0..7
    const int bcol = (tid & 31) * 4;    // 0..124

    const int tx = tid & 15;            // micro-tile col group
    const int ty = tid >> 4;            // micro-tile row group

    const float* Ablk = A + (size_t)m0 * K;
    const float* Bblk = B + n0;

    float acc[8][8];
    #pragma unroll
    for (int i = 0; i < 8; i++)
        #pragma unroll
        for (int j = 0; j < 8; j++) acc[i][j] = 0.f;

    for (int k0 = 0; k0 < K; k0 += 16) {
        // ---- load A tile (128 x 16) ----
        #pragma unroll
        for (int r = 0; r < 2; r++) {
            int row = arow + r * 64;
            float4 v = *(const float4*)(Ablk + (size_t)row * K + k0 + acol);
            As[acol + 0][row] = v.x;
            As[acol + 1][row] = v.y;
            As[acol + 2][row] = v.z;
            As[acol + 3][row] = v.w;
        }
        // ---- load B tile (16 x 128) ----
        #pragma unroll
        for (int r = 0; r < 2; r++) {
            int row = brow + r * 8;
            float4 v = *(const float4*)(Bblk + (size_t)(k0 + row) * ldb + bcol);
            *(float4*)&Bs[row][bcol] = v;
        }
        __syncthreads();

        // ---- compute 16 k-steps ----
        #pragma unroll
        for (int k = 0; k < 16; k++) {
            float a[8], b[8];
            *(float4*)&a[0] = *(const float4*)&As[k][ty * 4];
            *(float4*)&a[4] = *(const float4*)&As[k][64 + ty * 4];
            *(float4*)&b[0] = *(const float4*)&Bs[k][tx * 4];
            *(float4*)&b[4] = *(const float4*)&Bs[k][64 + tx * 4];
            #pragma unroll
            for (int i = 0; i < 8; i++)
                #pragma unroll
                for (int j = 0; j < 8; j++)
                    acc[i][j] = fmaf(a[i], b[j], acc[i][j]);
        }
        __syncthreads();
    }

    // preload the 8 bias values this thread touches
    float bv[8];
    #pragma unroll
    for (int h = 0; h < 2; h++)
        #pragma unroll
        for (int j = 0; j < 4; j++)
            bv[h * 4 + j] = bias[n0 + h * 64 + tx * 4 + j];

    if (EPI == 0) {
        // bias + relu, store
        #pragma unroll
        for (int i = 0; i < 8; i++) {
            int row = m0 + ((i < 4) ? (ty * 4 + i) : (64 + ty * 4 + (i - 4)));
            float* crow = C + (size_t)row * ldb + n0;
            #pragma unroll
            for (int h = 0; h < 2; h++) {
                float4 v;
                v.x = fmaxf(acc[i][h * 4 + 0] + bv[h * 4 + 0], 0.f);
                v.y = fmaxf(acc[i][h * 4 + 1] + bv[h * 4 + 1], 0.f);
                v.z = fmaxf(acc[i][h * 4 + 2] + bv[h * 4 + 2], 0.f);
                v.w = fmaxf(acc[i][h * 4 + 3] + bv[h * 4 + 3], 0.f);
                *(float4*)(crow + h * 64 + tx * 4) = v;
            }
        }
    } else {
        // bias + segment-sum via atomics into out[group][col]
        #pragma unroll
        for (int i = 0; i < 8; i++) {
            int row = m0 + ((i < 4) ? (ty * 4 + i) : (64 + ty * 4 + (i - 4)));
            int g = batch[row];
            float* orow = out + (size_t)g * D_OUT + n0;
            #pragma unroll
            for (int h = 0; h < 2; h++)
                #pragma unroll
                for (int j = 0; j < 4; j++)
                    atomicAdd(orow + h * 64 + tx * 4 + j,
                              acc[i][h * 4 + j] + bv[h * 4 + j]);
        }
    }
}

// ---------------------------------------------------------------------------
// In-place row LayerNorm over D_H=1024: one block (256 threads) per row.
// ---------------------------------------------------------------------------
__global__ void __launch_bounds__(256)
ln_kernel(float* __restrict__ X,
          const float* __restrict__ gamma,
          const float* __restrict__ beta)
{
    const int row = blockIdx.x;
    const int tid = threadIdx.x;
    float* x = X + (size_t)row * D_H;

    float4 v = *(const float4*)(x + tid * 4);
    float s  = v.x + v.y + v.z + v.w;
    float sq = v.x * v.x + v.y * v.y + v.z * v.z + v.w * v.w;

    // block reduce (sum, sumsq)
    #pragma unroll
    for (int o = 16; o > 0; o >>= 1) {
        s  += __shfl_xor_sync(0xffffffffu, s, o);
        sq += __shfl_xor_sync(0xffffffffu, sq, o);
    }
    __shared__ float2 red[8];
    const int w = tid >> 5, l = tid & 31;
    if (l == 0) red[w] = make_float2(s, sq);
    __syncthreads();
    if (w == 0) {
        float2 p = (l < 8) ? red[l] : make_float2(0.f, 0.f);
        s = p.x; sq = p.y;
        #pragma unroll
        for (int o = 4; o > 0; o >>= 1) {
            s  += __shfl_xor_sync(0xffffffffu, s, o);
            sq += __shfl_xor_sync(0xffffffffu, sq, o);
        }
        if (l == 0) red[0] = make_float2(s, sq);
    }
    __syncthreads();

    const float mean = red[0].x * (1.0f / D_H);
    const float var  = red[0].y * (1.0f / D_H) - mean * mean;
    const float inv  = rsqrtf(var + LN_EPS);

    float4 gg = *(const float4*)(gamma + tid * 4);
    float4 bb = *(const float4*)(beta  + tid * 4);
    float4 o;
    o.x = (v.x - mean) * inv * gg.x + bb.x;
    o.y = (v.y - mean) * inv * gg.y + bb.y;
    o.z = (v.z - mean) * inv * gg.z + bb.z;
    o.w = (v.w - mean) * inv * gg.w + bb.w;
    *(float4*)(x + tid * 4) = o;
}

// ---------------------------------------------------------------------------
// Small helper kernels
// ---------------------------------------------------------------------------
__global__ void zero_kernel(float* __restrict__ out)
{
    int i = blockIdx.x * blockDim.x + threadIdx.x;
    if (i < NUM_GROUPS * D_OUT) out[i] = 0.f;
    if (i < NUM_GROUPS) g_counts[i] = 0.f;
}

__global__ void count_kernel(const int* __restrict__ batch)
{
    int i = blockIdx.x * blockDim.x + threadIdx.x;
    if (i < N_ROWS) atomicAdd(&g_counts[batch[i]], 1.0f);
}

__global__ void finalize_kernel(float* __restrict__ out)
{
    int i = blockIdx.x * blockDim.x + threadIdx.x;
    if (i < NUM_GROUPS * D_OUT) out[i] = out[i] / g_counts[i / D_OUT];
}

// ---------------------------------------------------------------------------
// kernel_launch: graph-capturable sequence on the default stream.
// Inputs (metadata order): X, W1, b1, g1, be1, W2, b2, g2, be2, W3, b3, all_batch
// ---------------------------------------------------------------------------
extern "C" void kernel_launch(void* const* d_in, const int* in_sizes, int n_in,
                              void* d_out, int out_size)
{
    const float* X   = (const float*)d_in[0];
    const float* W1  = (const float*)d_in[1];
    const float* b1  = (const float*)d_in[2];
    const float* g1  = (const float*)d_in[3];
    const float* be1 = (const float*)d_in[4];
    const float* W2  = (const float*)d_in[5];
    const float* b2  = (const float*)d_in[6];
    const float* g2  = (const float*)d_in[7];
    const float* be2 = (const float*)d_in[8];
    const float* W3  = (const float*)d_in[9];
    const float* b3  = (const float*)d_in[10];
    const int*   batch = (const int*)d_in[11];
    float* outp = (float*)d_out;

    float *h1, *h2;
    cudaGetSymbolAddress((void**)&h1, g_h1);
    cudaGetSymbolAddress((void**)&h2, g_h2);

    // init output + counts
    zero_kernel<<<(NUM_GROUPS * D_OUT + 255) / 256, 256>>>(outp);
    count_kernel<<<(N_ROWS + 255) / 256, 256>>>(batch);

    // layer 1: h1 = relu(X @ W1 + b1); then LN in-place
    sgemm_fused<0><<<dim3(D_H / 128, N_ROWS / 128), 256>>>(
        X, W1, b1, h1, D_IN, D_H, nullptr, nullptr);
    ln_kernel<<<N_ROWS, 256>>>(h1, g1, be1);

    // layer 2: h2 = relu(h1 @ W2 + b2); then LN in-place
    sgemm_fused<0><<<dim3(D_H / 128, N_ROWS / 128), 256>>>(
        h1, W2, b2, h2, D_H, D_H, nullptr, nullptr);
    ln_kernel<<<N_ROWS, 256>>>(h2, g2, be2);

    // layer 3: segment-sum(h2 @ W3 + b3) into out via atomics
    sgemm_fused<1><<<dim3(D_OUT / 128, N_ROWS / 128), 256>>>(
        h2, W3, b3, nullptr, D_H, D_OUT, batch, outp);

    // mean = sum / count
    finalize_kernel<<<(NUM_GROUPS * D_OUT + 255) / 256, 256>>>(outp);
}

// round 2
// speedup vs baseline: 2.8593x; 2.8593x over previous
#include <cuda_runtime.h>
#include <cuda_bf16.h>
#include <cstdint>

// Problem constants
#define N_ROWS     131072
#define D_IN       512
#define D_H        1024
#define D_OUT      128
#define NUM_GROUPS 1024
#define LN_EPS     1e-5f

// ---------------------------------------------------------------------------
// Device scratch (no cudaMalloc allowed)
// ---------------------------------------------------------------------------
__device__ float g_h1[(size_t)N_ROWS * D_H];     // layer1 act (post-LN, tf32-rounded)
__device__ float g_h2[(size_t)N_ROWS * D_H];     // layer2 act (post-LN, tf32-rounded)
__device__ float g_xc[(size_t)N_ROWS * D_IN];    // X rounded to tf32
__device__ float g_w1[(size_t)D_IN * D_H];       // W1 rounded to tf32
__device__ float g_w2[(size_t)D_H * D_H];        // W2 rounded to tf32
__device__ float g_w3[(size_t)D_H * D_OUT];      // W3 rounded to tf32
__device__ float g_counts[NUM_GROUPS];

// ---------------------------------------------------------------------------
// Helpers
// ---------------------------------------------------------------------------
__device__ __forceinline__ float tf32_rna(float x) {
    uint32_t u;
    asm("cvt.rna.tf32.f32 %0, %1;" : "=r"(u) : "f"(x));
    return __uint_as_float(u);
}

__device__ __forceinline__ void cp_async16(uint32_t dst_smem, const void* src) {
    asm volatile("cp.async.cg.shared.global [%0], [%1], 16;\n"
                 :: "r"(dst_smem), "l"(src));
}
__device__ __forceinline__ void cp_commit() {
    asm volatile("cp.async.commit_group;\n" ::);
}
template <int N>
__device__ __forceinline__ void cp_wait() {
    asm volatile("cp.async.wait_group %0;\n" :: "n"(N));
}

__device__ __forceinline__ void mma_tf32(float* c, const uint32_t* a, const uint32_t* b) {
    asm volatile(
        "mma.sync.aligned.m16n8k8.row.col.f32.tf32.tf32.f32 "
        "{%0,%1,%2,%3}, {%4,%5,%6,%7}, {%8,%9}, {%0,%1,%2,%3};\n"
        : "+f"(c[0]), "+f"(c[1]), "+f"(c[2]), "+f"(c[3])
        : "r"(a[0]), "r"(a[1]), "r"(a[2]), "r"(a[3]), "r"(b[0]), "r"(b[1]));
}

// ---------------------------------------------------------------------------
// TF32 tensor-core GEMM, C[M,Ncols] = A[M,K] @ B[K,Ncols] + bias, fused epi:
//   EPI == 0 : C = relu(.), stored (ldc == ldb)
//   EPI == 1 : atomicAdd into out[batch[row]*D_OUT + col]  (segment sum)
// BM=BN=128, BK=32, 256 threads, 8 warps (2x4), warp tile 64x32,
// per-warp 4x4 m16n8k8 fragments, cp.async double-buffered smem.
// Inputs A,B must be pre-rounded to tf32 (rna) so MMA truncation is exact.
// Requires M%128==0, Ncols%128==0, K%32==0.
// smem: A stage [128][36] f32, B stage [32][136] f32, x2 stages = 71680 B.
// ---------------------------------------------------------------------------
#define A_STG 4608    // 128*36 floats per stage
#define B_STG 4352    // 32*136 floats per stage
#define B_BASE 9216   // 2*A_STG
#define GEMM_SMEM ((2 * (A_STG + B_STG)) * 4)

template <int EPI>
__global__ void __launch_bounds__(256, 2)
tf32_gemm(const float* __restrict__ A,
          const float* __restrict__ B,
          const float* __restrict__ bias,
          float* __restrict__ C,
          int K, int lda, int ldb,
          const int* __restrict__ batch,
          float* __restrict__ out)
{
    extern __shared__ float smem[];
    const uint32_t sb = (uint32_t)__cvta_generic_to_shared(smem);

    const int tid = threadIdx.x;
    const int m0 = blockIdx.y * 128;
    const int n0 = blockIdx.x * 128;

    const int wid  = tid >> 5, lane = tid & 31;
    const int wm   = wid & 1;           // warp row (0..1)   -> 64 rows
    const int wn   = wid >> 1;          // warp col (0..3)   -> 32 cols
    const int g    = lane >> 2;         // 0..7
    const int t    = lane & 3;          // 0..3

    float acc[4][4][4];
    #pragma unroll
    for (int i = 0; i < 4; i++)
        #pragma unroll
        for (int j = 0; j < 4; j++)
            #pragma unroll
            for (int r = 0; r < 4; r++) acc[i][j][r] = 0.f;

    const int iters = K >> 5;

    // ---- tile loader (cp.async) ----
    auto load_tiles = [&](int k0, int s) {
        #pragma unroll
        for (int c = 0; c < 4; c++) {
            int chunk = tid + c * 256;          // 0..1023
            int row = chunk >> 3, kc = (chunk & 7) * 4;
            cp_async16(sb + (uint32_t)(s * A_STG + row * 36 + kc) * 4,
                       A + (size_t)(m0 + row) * lda + k0 + kc);
        }
        #pragma unroll
        for (int c = 0; c < 4; c++) {
            int chunk = tid + c * 256;
            int kr = chunk >> 5, nc = (chunk & 31) * 4;
            cp_async16(sb + (uint32_t)(B_BASE + s * B_STG + kr * 136 + nc) * 4,
                       B + (size_t)(k0 + kr) * ldb + n0 + nc);
        }
        cp_commit();
    };

    load_tiles(0, 0);

    for (int it = 0; it < iters; it++) {
        const int s = it & 1;
        if (it + 1 < iters) {
            load_tiles((it + 1) * 32, s ^ 1);
            cp_wait<1>();
        } else {
            cp_wait<0>();
        }
        __syncthreads();

        const float* As = smem + s * A_STG;
        const float* Bs = smem + B_BASE + s * B_STG;

        #pragma unroll
        for (int ko = 0; ko < 32; ko += 8) {
            uint32_t a[4][4], b[4][2];
            #pragma unroll
            for (int i = 0; i < 4; i++) {
                const uint32_t* p =
                    (const uint32_t*)(As + (wm * 64 + i * 16 + g) * 36 + ko + t);
                a[i][0] = p[0];
                a[i][1] = p[8 * 36];
                a[i][2] = p[4];
                a[i][3] = p[8 * 36 + 4];
            }
            #pragma unroll
            for (int j = 0; j < 4; j++) {
                const uint32_t* p =
                    (const uint32_t*)(Bs + (ko + t) * 136 + wn * 32 + j * 8 + g);
                b[j][0] = p[0];
                b[j][1] = p[4 * 136];
            }
            #pragma unroll
            for (int i = 0; i < 4; i++)
                #pragma unroll
                for (int j = 0; j < 4; j++)
                    mma_tf32(acc[i][j], a[i], b[j]);
        }
        __syncthreads();
    }

    // bias values this thread touches: cols wn*32 + j*8 + 2t, +1
    float bv[4][2];
    #pragma unroll
    for (int j = 0; j < 4; j++) {
        int col = n0 + wn * 32 + j * 8 + 2 * t;
        bv[j][0] = bias[col];
        bv[j][1] = bias[col + 1];
    }

    if (EPI == 0) {
        #pragma unroll
        for (int i = 0; i < 4; i++) {
            int r0 = m0 + wm * 64 + i * 16 + g;
            #pragma unroll
            for (int j = 0; j < 4; j++) {
                int col = n0 + wn * 32 + j * 8 + 2 * t;
                float2 v0, v1;
                v0.x = fmaxf(acc[i][j][0] + bv[j][0], 0.f);
                v0.y = fmaxf(acc[i][j][1] + bv[j][1], 0.f);
                v1.x = fmaxf(acc[i][j][2] + bv[j][0], 0.f);
                v1.y = fmaxf(acc[i][j][3] + bv[j][1], 0.f);
                *(float2*)(C + (size_t)r0 * ldb + col)       = v0;
                *(float2*)(C + (size_t)(r0 + 8) * ldb + col) = v1;
            }
        }
    } else {
        #pragma unroll
        for (int i = 0; i < 4; i++) {
            int r0 = m0 + wm * 64 + i * 16 + g;
            int g0 = batch[r0], g1 = batch[r0 + 8];
            float* o0 = out + (size_t)g0 * D_OUT;
            float* o1 = out + (size_t)g1 * D_OUT;
            #pragma unroll
            for (int j = 0; j < 4; j++) {
                int col = wn * 32 + j * 8 + 2 * t;   // n0 == 0 for layer 3
                atomicAdd(o0 + col,     acc[i][j][0] + bv[j][0]);
                atomicAdd(o0 + col + 1, acc[i][j][1] + bv[j][1]);
                atomicAdd(o1 + col,     acc[i][j][2] + bv[j][0]);
                atomicAdd(o1 + col + 1, acc[i][j][3] + bv[j][1]);
            }
        }
    }
}

// ---------------------------------------------------------------------------
// In-place row LayerNorm over D_H=1024; output rounded to tf32 (rna) so the
// next GEMM's MMA truncation is exact.
// ---------------------------------------------------------------------------
__global__ void __launch_bounds__(256)
ln_kernel(float* __restrict__ X,
          const float* __restrict__ gamma,
          const float* __restrict__ beta)
{
    const int row = blockIdx.x;
    const int tid = threadIdx.x;
    float* x = X + (size_t)row * D_H;

    float4 v = *(const float4*)(x + tid * 4);
    float s  = v.x + v.y + v.z + v.w;
    float sq = v.x * v.x + v.y * v.y + v.z * v.z + v.w * v.w;

    #pragma unroll
    for (int o = 16; o > 0; o >>= 1) {
        s  += __shfl_xor_sync(0xffffffffu, s, o);
        sq += __shfl_xor_sync(0xffffffffu, sq, o);
    }
    __shared__ float2 red[8];
    const int w = tid >> 5, l = tid & 31;
    if (l == 0) red[w] = make_float2(s, sq);
    __syncthreads();
    if (w == 0) {
        float2 p = (l < 8) ? red[l] : make_float2(0.f, 0.f);
        s = p.x; sq = p.y;
        #pragma unroll
        for (int o = 4; o > 0; o >>= 1) {
            s  += __shfl_xor_sync(0xffffffffu, s, o);
            sq += __shfl_xor_sync(0xffffffffu, sq, o);
        }
        if (l == 0) red[0] = make_float2(s, sq);
    }
    __syncthreads();

    const float mean = red[0].x * (1.0f / D_H);
    const float var  = red[0].y * (1.0f / D_H) - mean * mean;
    const float inv  = rsqrtf(var + LN_EPS);

    float4 gg = *(const float4*)(gamma + tid * 4);
    float4 bb = *(const float4*)(beta  + tid * 4);
    float4 o;
    o.x = tf32_rna((v.x - mean) * inv * gg.x + bb.x);
    o.y = tf32_rna((v.y - mean) * inv * gg.y + bb.y);
    o.z = tf32_rna((v.z - mean) * inv * gg.z + bb.z);
    o.w = tf32_rna((v.w - mean) * inv * gg.w + bb.w);
    *(float4*)(x + tid * 4) = o;
}

// ---------------------------------------------------------------------------
// Small helper kernels
// ---------------------------------------------------------------------------
__global__ void cvt_kernel(const float* __restrict__ src,
                           float* __restrict__ dst, int n4)
{
    int i = blockIdx.x * blockDim.x + threadIdx.x;
    if (i < n4) {
        float4 v = ((const float4*)src)[i];
        v.x = tf32_rna(v.x); v.y = tf32_rna(v.y);
        v.z = tf32_rna(v.z); v.w = tf32_rna(v.w);
        ((float4*)dst)[i] = v;
    }
}

__global__ void zero_kernel(float* __restrict__ out)
{
    int i = blockIdx.x * blockDim.x + threadIdx.x;
    if (i < NUM_GROUPS * D_OUT) out[i] = 0.f;
    if (i < NUM_GROUPS) g_counts[i] = 0.f;
}

__global__ void count_kernel(const int* __restrict__ batch)
{
    int i = blockIdx.x * blockDim.x + threadIdx.x;
    if (i < N_ROWS) atomicAdd(&g_counts[batch[i]], 1.0f);
}

__global__ void finalize_kernel(float* __restrict__ out)
{
    int i = blockIdx.x * blockDim.x + threadIdx.x;
    if (i < NUM_GROUPS * D_OUT) out[i] = out[i] / g_counts[i / D_OUT];
}

// ---------------------------------------------------------------------------
// kernel_launch
// Inputs: X, W1, b1, g1, be1, W2, b2, g2, be2, W3, b3, all_batch
// ---------------------------------------------------------------------------
extern "C" void kernel_launch(void* const* d_in, const int* in_sizes, int n_in,
                              void* d_out, int out_size)
{
    const float* X   = (const float*)d_in[0];
    const float* W1  = (const float*)d_in[1];
    const float* b1  = (const float*)d_in[2];
    const float* g1  = (const float*)d_in[3];
    const float* be1 = (const float*)d_in[4];
    const float* W2  = (const float*)d_in[5];
    const float* b2  = (const float*)d_in[6];
    const float* g2  = (const float*)d_in[7];
    const float* be2 = (const float*)d_in[8];
    const float* W3  = (const float*)d_in[9];
    const float* b3  = (const float*)d_in[10];
    const int*   batch = (const int*)d_in[11];
    float* outp = (float*)d_out;

    float *h1, *h2, *xc, *w1c, *w2c, *w3c;
    cudaGetSymbolAddress((void**)&h1,  g_h1);
    cudaGetSymbolAddress((void**)&h2,  g_h2);
    cudaGetSymbolAddress((void**)&xc,  g_xc);
    cudaGetSymbolAddress((void**)&w1c, g_w1);
    cudaGetSymbolAddress((void**)&w2c, g_w2);
    cudaGetSymbolAddress((void**)&w3c, g_w3);

    cudaFuncSetAttribute(tf32_gemm<0>,
        cudaFuncAttributeMaxDynamicSharedMemorySize, GEMM_SMEM);
    cudaFuncSetAttribute(tf32_gemm<1>,
        cudaFuncAttributeMaxDynamicSharedMemorySize, GEMM_SMEM);

    // round inputs/weights to tf32 (rna) once
    {
        int n4;
        n4 = (N_ROWS * D_IN) / 4;
        cvt_kernel<<<(n4 + 255) / 256, 256>>>(X,  xc,  n4);
        n4 = (D_IN * D_H) / 4;
        cvt_kernel<<<(n4 + 255) / 256, 256>>>(W1, w1c, n4);
        n4 = (D_H * D_H) / 4;
        cvt_kernel<<<(n4 + 255) / 256, 256>>>(W2, w2c, n4);
        n4 = (D_H * D_OUT) / 4;
        cvt_kernel<<<(n4 + 255) / 256, 256>>>(W3, w3c, n4);
    }

    // init output + counts
    zero_kernel<<<(NUM_GROUPS * D_OUT + 255) / 256, 256>>>(outp);
    count_kernel<<<(N_ROWS + 255) / 256, 256>>>(batch);

    // layer 1: h1 = relu(Xc @ W1c + b1); LN in-place (tf32-rounded out)
    tf32_gemm<0><<<dim3(D_H / 128, N_ROWS / 128), 256, GEMM_SMEM>>>(
        xc, w1c, b1, h1, D_IN, D_IN, D_H, nullptr, nullptr);
    ln_kernel<<<N_ROWS, 256>>>(h1, g1, be1);

    // layer 2: h2 = relu(h1 @ W2c + b2); LN in-place
    tf32_gemm<0><<<dim3(D_H / 128, N_ROWS / 128), 256, GEMM_SMEM>>>(
        h1, w2c, b2, h2, D_H, D_H, D_H, nullptr, nullptr);
    ln_kernel<<<N_ROWS, 256>>>(h2, g2, be2);

    // layer 3: segment-sum(h2 @ W3c + b3) via atomics
    tf32_gemm<1><<<dim3(D_OUT / 128, N_ROWS / 128), 256, GEMM_SMEM>>>(
        h2, w3c, b3, nullptr, D_H, D_H, D_OUT, batch, outp);

    // mean = sum / count
    finalize_kernel<<<(NUM_GROUPS * D_OUT + 255) / 256, 256>>>(outp);
}